// round 1
// baseline (speedup 1.0000x reference)
#include <cuda_runtime.h>
#include <cstdint>

#define UNITS   2048
#define IN_DIM  512
#define TSTEPS  8192
#define NCTA    128
#define SCAN_THREADS 256

// 64 MB staging buffer for xin = x @ wax^T + ba  (allowed: __device__ global)
__device__ float g_xin[(size_t)TSTEPS * UNITS];
// per-CTA monotonic step stamps for the grid-wide release/acquire barrier
__device__ unsigned g_flags[NCTA];

__device__ __forceinline__ unsigned ld_acquire_gpu(const unsigned* p) {
    unsigned v;
    asm volatile("ld.acquire.gpu.u32 %0, [%1];" : "=r"(v) : "l"(p) : "memory");
    return v;
}
__device__ __forceinline__ void st_release_gpu(unsigned* p, unsigned v) {
    asm volatile("st.release.gpu.u32 [%0], %1;" :: "l"(p), "r"(v) : "memory");
}

// ---------------------------------------------------------------------------
// Init: zero the barrier stamps (must run every graph replay, before the scan)
// ---------------------------------------------------------------------------
__global__ void init_kernel() {
    if (threadIdx.x < NCTA) g_flags[threadIdx.x] = 0u;
}

// ---------------------------------------------------------------------------
// Phase 1: xin[t][u] = sum_d x[t][d] * wax[u][d] + ba[u]
// NT GEMM, BM=128 (t), BN=64 (u), BK=16, 256 threads, TM=8, TN=4
// ---------------------------------------------------------------------------
__global__ __launch_bounds__(256) void xin_gemm_kernel(
    const float* __restrict__ x,     // [8192][512]
    const float* __restrict__ wax,   // [2048][512]
    const float* __restrict__ ba)    // [2048]
{
    __shared__ float As[16][128 + 4];  // [k][m]
    __shared__ float Bs[16][64 + 4];   // [k][n]

    const int tid = threadIdx.x;
    const int bm = blockIdx.y * 128;
    const int bn = blockIdx.x * 64;
    const int tx = tid & 15;   // n: 4 cols each
    const int ty = tid >> 4;   // m: 8 rows each

    float acc[8][4];
#pragma unroll
    for (int i = 0; i < 8; i++)
#pragma unroll
        for (int j = 0; j < 4; j++) acc[i][j] = 0.f;

    const int lr = tid >> 2;          // 0..63
    const int lc = (tid & 3) * 4;     // k col 0/4/8/12

    for (int k0 = 0; k0 < IN_DIM; k0 += 16) {
        float4 a0 = *(const float4*)&x[(size_t)(bm + lr) * IN_DIM + k0 + lc];
        float4 a1 = *(const float4*)&x[(size_t)(bm + lr + 64) * IN_DIM + k0 + lc];
        float4 b0 = *(const float4*)&wax[(size_t)(bn + lr) * IN_DIM + k0 + lc];

        As[lc + 0][lr] = a0.x; As[lc + 1][lr] = a0.y;
        As[lc + 2][lr] = a0.z; As[lc + 3][lr] = a0.w;
        As[lc + 0][lr + 64] = a1.x; As[lc + 1][lr + 64] = a1.y;
        As[lc + 2][lr + 64] = a1.z; As[lc + 3][lr + 64] = a1.w;
        Bs[lc + 0][lr] = b0.x; Bs[lc + 1][lr] = b0.y;
        Bs[lc + 2][lr] = b0.z; Bs[lc + 3][lr] = b0.w;
        __syncthreads();

#pragma unroll
        for (int kk = 0; kk < 16; kk++) {
            float4 av0 = *(const float4*)&As[kk][ty * 8];
            float4 av1 = *(const float4*)&As[kk][ty * 8 + 4];
            float4 bv  = *(const float4*)&Bs[kk][tx * 4];
            float a[8] = {av0.x, av0.y, av0.z, av0.w, av1.x, av1.y, av1.z, av1.w};
            float b[4] = {bv.x, bv.y, bv.z, bv.w};
#pragma unroll
            for (int i = 0; i < 8; i++)
#pragma unroll
                for (int j = 0; j < 4; j++)
                    acc[i][j] = fmaf(a[i], b[j], acc[i][j]);
        }
        __syncthreads();
    }

    float4 bav = *(const float4*)&ba[bn + tx * 4];
#pragma unroll
    for (int i = 0; i < 8; i++) {
        float4 c;
        c.x = acc[i][0] + bav.x;
        c.y = acc[i][1] + bav.y;
        c.z = acc[i][2] + bav.z;
        c.w = acc[i][3] + bav.w;
        *(float4*)&g_xin[(size_t)(bm + ty * 8 + i) * UNITS + bn + tx * 4] = c;
    }
}

// ---------------------------------------------------------------------------
// Phase 2: persistent scan kernel.
// 128 CTAs (all co-resident, 1/SM), 16 rows of waa per CTA held in registers
// (8 warps x 2 rows x 64 floats/lane). Per step:
//   poll peer stamps (acquire) -> stage a_{t-1} (= out[t-1]) into SMEM ->
//   register FMA loop -> warp butterfly reduce -> tanh -> publish out[t] ->
//   release stamp.
// out[] itself is the state history; t=0 uses a zero state.
// ---------------------------------------------------------------------------
__global__ __launch_bounds__(SCAN_THREADS, 1) void scan_kernel(
    const float* __restrict__ waa,   // [2048][2048]
    float* __restrict__ out)         // [8192][2048]
{
    __shared__ float a_sm[UNITS];    // 8 KB current state
    float4* a_sm4 = (float4*)a_sm;

    const int tid  = threadIdx.x;
    const int lane = tid & 31;
    const int warp = tid >> 5;               // 0..7
    const int cta  = blockIdx.x;             // 0..127
    const int row0 = cta * 16 + warp * 2;    // this warp's 2 output rows

    // Preload this lane's waa slice: rows row0/row0+1, cols {128k + 4*lane .. +3}
    float4 w0[16], w1[16];
#pragma unroll
    for (int k = 0; k < 16; k++) {
        w0[k] = *(const float4*)&waa[(size_t)row0 * UNITS + k * 128 + lane * 4];
        w1[k] = *(const float4*)&waa[(size_t)(row0 + 1) * UNITS + k * 128 + lane * 4];
    }

    for (int t = 0; t < TSTEPS; t++) {
        if (t == 0) {
            for (int i = tid; i < UNITS / 4; i += SCAN_THREADS)
                a_sm4[i] = make_float4(0.f, 0.f, 0.f, 0.f);
        } else {
            if (warp == 0) {
                const unsigned target = (unsigned)t;
                for (;;) {
                    unsigned f0 = ld_acquire_gpu(&g_flags[lane]);
                    unsigned f1 = ld_acquire_gpu(&g_flags[lane + 32]);
                    unsigned f2 = ld_acquire_gpu(&g_flags[lane + 64]);
                    unsigned f3 = ld_acquire_gpu(&g_flags[lane + 96]);
                    unsigned m = min(min(f0, f1), min(f2, f3));
                    if (__all_sync(0xffffffffu, m >= target)) break;
                }
            }
            __syncthreads();   // acquire by warp0 now orders the whole CTA
            const float4* aprev = (const float4*)(out + (size_t)(t - 1) * UNITS);
            for (int i = tid; i < UNITS / 4; i += SCAN_THREADS)
                a_sm4[i] = aprev[i];
        }

        // prefetch this warp's xin pair (rows row0, row0+1 are adjacent)
        float2 xv;
        if (lane == 0)
            xv = *(const float2*)&g_xin[(size_t)t * UNITS + row0];

        __syncthreads();       // a_sm ready

        // register matvec: 2 rows x 2048 cols, 128 FFMA per lane
        float s0 = 0.f, s1 = 0.f;
#pragma unroll
        for (int k = 0; k < 16; k++) {
            float4 av = a_sm4[k * 32 + lane];
            s0 = fmaf(w0[k].x, av.x, s0);
            s0 = fmaf(w0[k].y, av.y, s0);
            s0 = fmaf(w0[k].z, av.z, s0);
            s0 = fmaf(w0[k].w, av.w, s0);
            s1 = fmaf(w1[k].x, av.x, s1);
            s1 = fmaf(w1[k].y, av.y, s1);
            s1 = fmaf(w1[k].z, av.z, s1);
            s1 = fmaf(w1[k].w, av.w, s1);
        }

        // butterfly reduce both sums
#pragma unroll
        for (int off = 16; off; off >>= 1) {
            s0 += __shfl_xor_sync(0xffffffffu, s0, off);
            s1 += __shfl_xor_sync(0xffffffffu, s1, off);
        }

        if (lane == 0) {
            float2 h;
            h.x = tanhf(s0 + xv.x);
            h.y = tanhf(s1 + xv.y);
            *(float2*)&out[(size_t)t * UNITS + row0] = h;
        }

        __syncthreads();       // all 8 warps' stores ordered before the release
        if (tid == 0)
            st_release_gpu(&g_flags[cta], (unsigned)(t + 1));
    }
}

// ---------------------------------------------------------------------------
extern "C" void kernel_launch(void* const* d_in, const int* in_sizes, int n_in,
                              void* d_out, int out_size) {
    const float* x   = (const float*)d_in[0];   // (1, 8192, 512)
    const float* waa = (const float*)d_in[1];   // (2048, 2048)
    const float* wax = (const float*)d_in[2];   // (2048, 512)
    const float* ba  = (const float*)d_in[3];   // (2048, 1)
    float* out = (float*)d_out;                 // (1, 8192, 2048)

    init_kernel<<<1, 128>>>();

    dim3 grid(UNITS / 64, TSTEPS / 128);        // (32, 64)
    xin_gemm_kernel<<<grid, 256>>>(x, wax, ba);

    scan_kernel<<<NCTA, SCAN_THREADS>>>(waa, out);
}